// round 4
// baseline (speedup 1.0000x reference)
#include <cuda_runtime.h>
#include <cuda_bf16.h>
#include <cstddef>

#define NUM_CLASS 1000
#define DIMS      2048
#define HEADSZ    256
#define NSAMP     16384
#define ALPHA_F   0.999f

#define SAMPLES_PER_BLOCK 8
#define NLOSS_BLOCKS (NSAMP / SAMPLES_PER_BLOCK)   // 2048

// Scratch (__device__ globals; zero-init is the valid empty state, and the
// kernels self-reset everything for the next graph replay).
__device__ int    g_last_idx[NUM_CLASS];   // stores sample_index+1; 0 = empty
__device__ double g_loss_accum;
__device__ int    g_ticket;

// ---------------------------------------------------------------------------
// Kernel A: last-write-wins index per class, from labels only (64 KB read).
// ---------------------------------------------------------------------------
__global__ __launch_bounds__(512) void ema_lastidx_kernel(
    const int* __restrict__ labels)
{
    const int n = blockIdx.x * 512 + threadIdx.x;
    if (n < NSAMP) {
        atomicMax(&g_last_idx[labels[n]], n + 1);
    }
}

// ---------------------------------------------------------------------------
// Kernel B (fused):
//   blocks [0, NUM_CLASS)            : EMA scatter update (one class each)
//   blocks [NUM_CLASS, +NLOSS_BLOCKS): SSE for 8 contiguous samples each
// Update blocks go first so their traffic overlaps the loss stream from
// wave 0. Last loss block to retire finalizes loss into out[0].
// ---------------------------------------------------------------------------
__global__ __launch_bounds__(256) void ema_fused_kernel(
    const float* __restrict__ x,
    const int*   __restrict__ labels,
    const float* __restrict__ centers,
    float*       __restrict__ out_loss,      // may be null
    float*       __restrict__ out_centers)
{
    const int b = blockIdx.x;
    const int t = threadIdx.x;

    if (b < NUM_CLASS) {
        // ---------------- update path: one class per block ----------------
        const int c       = b;
        const int last_p1 = g_last_idx[c];   // final: kernel A completed

        const float4* __restrict__ cr = reinterpret_cast<const float4*>(centers + (size_t)c * DIMS);
        float* __restrict__ oc = out_centers + (size_t)c * DIMS;

        if (last_p1 > 0) {
            const float4* __restrict__ xr =
                reinterpret_cast<const float4*>(x + (size_t)(last_p1 - 1) * DIMS);
            const float beta = 1.0f - ALPHA_F;
            const float4 cv0 = cr[t];
            const float4 cv1 = cr[t + 256];
            const float4 xv0 = xr[t];
            const float4 xv1 = xr[t + 256];
            int base = t * 4;
            oc[base + 0] = ALPHA_F * cv0.x + beta * xv0.x;
            oc[base + 1] = ALPHA_F * cv0.y + beta * xv0.y;
            oc[base + 2] = ALPHA_F * cv0.z + beta * xv0.z;
            oc[base + 3] = ALPHA_F * cv0.w + beta * xv0.w;
            base += 1024;
            oc[base + 0] = ALPHA_F * cv1.x + beta * xv1.x;
            oc[base + 1] = ALPHA_F * cv1.y + beta * xv1.y;
            oc[base + 2] = ALPHA_F * cv1.z + beta * xv1.z;
            oc[base + 3] = ALPHA_F * cv1.w + beta * xv1.w;
        } else {
            const float4 cv0 = cr[t];
            const float4 cv1 = cr[t + 256];
            int base = t * 4;
            oc[base + 0] = cv0.x; oc[base + 1] = cv0.y;
            oc[base + 2] = cv0.z; oc[base + 3] = cv0.w;
            base += 1024;
            oc[base + 0] = cv1.x; oc[base + 1] = cv1.y;
            oc[base + 2] = cv1.z; oc[base + 3] = cv1.w;
        }

        __syncthreads();
        if (t == 0) g_last_idx[c] = 0;   // self-reset for next replay
        return;
    }

    // ---------------- loss path: 8 contiguous samples per block ----------------
    const int bi   = b - NUM_CLASS;
    const int base = bi * SAMPLES_PER_BLOCK;

    // All 8 labels up front (uniform broadcast loads) — removes the per-iter
    // label -> center-address dependency from the loop's critical path.
    const int4* __restrict__ lp = reinterpret_cast<const int4*>(labels + base);
    const int4 L0 = lp[0];
    const int4 L1 = lp[1];
    int lab[SAMPLES_PER_BLOCK] = {L0.x, L0.y, L0.z, L0.w, L1.x, L1.y, L1.z, L1.w};

    float s = 0.0f;
#pragma unroll
    for (int i = 0; i < SAMPLES_PER_BLOCK; i += 2) {
        const float4* __restrict__ xr0 =
            reinterpret_cast<const float4*>(x + (size_t)(base + i) * DIMS);
        const float4* __restrict__ xr1 =
            reinterpret_cast<const float4*>(x + (size_t)(base + i + 1) * DIMS);
        const float4* __restrict__ cr0 =
            reinterpret_cast<const float4*>(centers + (size_t)lab[i] * DIMS);
        const float4* __restrict__ cr1 =
            reinterpret_cast<const float4*>(centers + (size_t)lab[i + 1] * DIMS);

        // Front-batch all 8 loads for max MLP.
        const float4 a0 = xr0[t];
        const float4 a1 = xr0[t + 256];
        const float4 a2 = xr1[t];
        const float4 a3 = xr1[t + 256];
        const float4 b0 = cr0[t];
        const float4 b1 = cr0[t + 256];
        const float4 b2 = cr1[t];
        const float4 b3 = cr1[t + 256];

        float d;
        s += (d = a0.x - b0.x) * d; s += (d = a0.y - b0.y) * d;
        s += (d = a0.z - b0.z) * d; s += (d = a0.w - b0.w) * d;
        s += (d = a1.x - b1.x) * d; s += (d = a1.y - b1.y) * d;
        s += (d = a1.z - b1.z) * d; s += (d = a1.w - b1.w) * d;
        s += (d = a2.x - b2.x) * d; s += (d = a2.y - b2.y) * d;
        s += (d = a2.z - b2.z) * d; s += (d = a2.w - b2.w) * d;
        s += (d = a3.x - b3.x) * d; s += (d = a3.y - b3.y) * d;
        s += (d = a3.z - b3.z) * d; s += (d = a3.w - b3.w) * d;
    }

    // warp reduce
#pragma unroll
    for (int o = 16; o > 0; o >>= 1) s += __shfl_xor_sync(0xFFFFFFFFu, s, o);

    __shared__ float warp_s[8];
    if ((t & 31) == 0) warp_s[t >> 5] = s;
    __syncthreads();

    if (t == 0) {
        float v = warp_s[0] + warp_s[1] + warp_s[2] + warp_s[3]
                + warp_s[4] + warp_s[5] + warp_s[6] + warp_s[7];
        atomicAdd(&g_loss_accum, (double)v);
        __threadfence();
        const int old = atomicAdd(&g_ticket, 1);
        if (old == NLOSS_BLOCKS - 1) {
            if (out_loss != nullptr) {
                *out_loss = (float)(g_loss_accum / ((double)NSAMP * (double)HEADSZ));
            }
            g_loss_accum = 0.0;
            g_ticket     = 0;
        }
    }
}

// ---------------------------------------------------------------------------
extern "C" void kernel_launch(void* const* d_in, const int* in_sizes, int n_in,
                              void* d_out, int out_size) {
    const float* x       = (const float*)d_in[0];
    const int*   labels  = (const int*)  d_in[1];
    const float* centers = (const float*)d_in[2];

    float* out = (float*)d_out;
    const int centers_elems = NUM_CLASS * DIMS;          // 2,048,000
    float* out_centers = out + (out_size - centers_elems);
    float* out_loss    = (out_size > centers_elems) ? out : nullptr;

    ema_lastidx_kernel<<<(NSAMP + 511) / 512, 512>>>(labels);
    ema_fused_kernel<<<NUM_CLASS + NLOSS_BLOCKS, 256>>>(x, labels, centers,
                                                        out_loss, out_centers);
}

// round 5
// speedup vs baseline: 1.0990x; 1.0990x over previous
#include <cuda_runtime.h>
#include <cuda_bf16.h>
#include <cstddef>

#define NUM_CLASS 1000
#define DIMS      2048
#define HEADSZ    256
#define NSAMP     16384
#define ALPHA_F   0.999f

#define SAMPLES_PER_BLOCK 8
#define NPAIRS (SAMPLES_PER_BLOCK / 2)             // 4
#define NLOSS_BLOCKS (NSAMP / SAMPLES_PER_BLOCK)   // 2048

// Scratch (__device__ globals; zero-init is the valid empty state, and the
// kernels self-reset everything for the next graph replay).
__device__ int    g_last_idx[NUM_CLASS];   // stores sample_index+1; 0 = empty
__device__ double g_loss_accum;
__device__ int    g_ticket;

// ---------------------------------------------------------------------------
// Kernel A: last-write-wins index per class, from labels only (64 KB read).
// ---------------------------------------------------------------------------
__global__ __launch_bounds__(512) void ema_lastidx_kernel(
    const int* __restrict__ labels)
{
    const int n = blockIdx.x * 512 + threadIdx.x;
    if (n < NSAMP) {
        atomicMax(&g_last_idx[labels[n]], n + 1);
    }
}

// ---------------------------------------------------------------------------
// Kernel B (fused):
//   blocks [0, NUM_CLASS)            : EMA scatter update (one class each)
//   blocks [NUM_CLASS, +NLOSS_BLOCKS): SSE for 8 samples, double-buffered
// Loss loop is software-pipelined: loads of pair p+1 issue before the FMAs of
// pair p, so each warp keeps 8-16 LDG.128 in flight continuously instead of
// burst-8-then-stall (the R4 bottleneck: DRAM stuck at 62%).
// ---------------------------------------------------------------------------
__global__ __launch_bounds__(256, 3) void ema_fused_kernel(
    const float* __restrict__ x,
    const int*   __restrict__ labels,
    const float* __restrict__ centers,
    float*       __restrict__ out_loss,      // may be null
    float*       __restrict__ out_centers)
{
    const int b = blockIdx.x;
    const int t = threadIdx.x;

    if (b < NUM_CLASS) {
        // ---------------- update path: one class per block ----------------
        const int c       = b;
        const int last_p1 = g_last_idx[c];   // final: kernel A completed

        const float4* __restrict__ cr = reinterpret_cast<const float4*>(centers + (size_t)c * DIMS);
        float* __restrict__ oc = out_centers + (size_t)c * DIMS;

        if (last_p1 > 0) {
            const float4* __restrict__ xr =
                reinterpret_cast<const float4*>(x + (size_t)(last_p1 - 1) * DIMS);
            const float beta = 1.0f - ALPHA_F;
            const float4 cv0 = cr[t];
            const float4 cv1 = cr[t + 256];
            const float4 xv0 = xr[t];
            const float4 xv1 = xr[t + 256];
            int base = t * 4;
            oc[base + 0] = ALPHA_F * cv0.x + beta * xv0.x;
            oc[base + 1] = ALPHA_F * cv0.y + beta * xv0.y;
            oc[base + 2] = ALPHA_F * cv0.z + beta * xv0.z;
            oc[base + 3] = ALPHA_F * cv0.w + beta * xv0.w;
            base += 1024;
            oc[base + 0] = ALPHA_F * cv1.x + beta * xv1.x;
            oc[base + 1] = ALPHA_F * cv1.y + beta * xv1.y;
            oc[base + 2] = ALPHA_F * cv1.z + beta * xv1.z;
            oc[base + 3] = ALPHA_F * cv1.w + beta * xv1.w;
        } else {
            const float4 cv0 = cr[t];
            const float4 cv1 = cr[t + 256];
            int base = t * 4;
            oc[base + 0] = cv0.x; oc[base + 1] = cv0.y;
            oc[base + 2] = cv0.z; oc[base + 3] = cv0.w;
            base += 1024;
            oc[base + 0] = cv1.x; oc[base + 1] = cv1.y;
            oc[base + 2] = cv1.z; oc[base + 3] = cv1.w;
        }

        __syncthreads();
        if (t == 0) g_last_idx[c] = 0;   // self-reset for next replay
        return;
    }

    // ------------- loss path: 8 samples, 4 pairs, 2-deep pipeline -------------
    const int bi   = b - NUM_CLASS;
    const int base = bi * SAMPLES_PER_BLOCK;

    // All 8 labels up front (uniform broadcast loads).
    const int4* __restrict__ lp = reinterpret_cast<const int4*>(labels + base);
    const int4 L0 = lp[0];
    const int4 L1 = lp[1];
    const int lab[SAMPLES_PER_BLOCK] = {L0.x, L0.y, L0.z, L0.w, L1.x, L1.y, L1.z, L1.w};

    // Two register buffers of 8 float4 each.
    float4 ax0[2], ax1[2], ax2[2], ax3[2];   // x:   [buf] sample0{lo,hi} sample1{lo,hi}
    float4 bx0[2], bx1[2], bx2[2], bx3[2];   // c

    // Issue loads for pair p into buffer buf.
#define LOAD_PAIR(p, buf)                                                        \
    do {                                                                         \
        const float4* __restrict__ xr0 =                                         \
            reinterpret_cast<const float4*>(x + (size_t)(base + 2 * (p)) * DIMS);\
        const float4* __restrict__ xr1 =                                         \
            reinterpret_cast<const float4*>(x + (size_t)(base + 2 * (p) + 1) * DIMS);\
        const float4* __restrict__ cr0 =                                         \
            reinterpret_cast<const float4*>(centers + (size_t)lab[2 * (p)] * DIMS);\
        const float4* __restrict__ cr1 =                                         \
            reinterpret_cast<const float4*>(centers + (size_t)lab[2 * (p) + 1] * DIMS);\
        ax0[buf] = xr0[t];       ax1[buf] = xr0[t + 256];                        \
        ax2[buf] = xr1[t];       ax3[buf] = xr1[t + 256];                        \
        bx0[buf] = cr0[t];       bx1[buf] = cr0[t + 256];                        \
        bx2[buf] = cr1[t];       bx3[buf] = cr1[t + 256];                        \
    } while (0)

#define SQD(a, b)                                                                \
    ((a.x - b.x) * (a.x - b.x) + (a.y - b.y) * (a.y - b.y) +                     \
     (a.z - b.z) * (a.z - b.z) + (a.w - b.w) * (a.w - b.w))

    float s = 0.0f;
    LOAD_PAIR(0, 0);
#pragma unroll
    for (int p = 0; p < NPAIRS; ++p) {
        const int cur = p & 1;
        if (p + 1 < NPAIRS) {
            LOAD_PAIR(p + 1, (p + 1) & 1);   // loads issue before pair p's FMAs
        }
        s += SQD(ax0[cur], bx0[cur]);
        s += SQD(ax1[cur], bx1[cur]);
        s += SQD(ax2[cur], bx2[cur]);
        s += SQD(ax3[cur], bx3[cur]);
    }
#undef LOAD_PAIR
#undef SQD

    // warp reduce
#pragma unroll
    for (int o = 16; o > 0; o >>= 1) s += __shfl_xor_sync(0xFFFFFFFFu, s, o);

    __shared__ float warp_s[8];
    if ((t & 31) == 0) warp_s[t >> 5] = s;
    __syncthreads();

    if (t == 0) {
        float v = warp_s[0] + warp_s[1] + warp_s[2] + warp_s[3]
                + warp_s[4] + warp_s[5] + warp_s[6] + warp_s[7];
        atomicAdd(&g_loss_accum, (double)v);
        __threadfence();
        const int old = atomicAdd(&g_ticket, 1);
        if (old == NLOSS_BLOCKS - 1) {
            if (out_loss != nullptr) {
                *out_loss = (float)(g_loss_accum / ((double)NSAMP * (double)HEADSZ));
            }
            g_loss_accum = 0.0;
            g_ticket     = 0;
        }
    }
}

// ---------------------------------------------------------------------------
extern "C" void kernel_launch(void* const* d_in, const int* in_sizes, int n_in,
                              void* d_out, int out_size) {
    const float* x       = (const float*)d_in[0];
    const int*   labels  = (const int*)  d_in[1];
    const float* centers = (const float*)d_in[2];

    float* out = (float*)d_out;
    const int centers_elems = NUM_CLASS * DIMS;          // 2,048,000
    float* out_centers = out + (out_size - centers_elems);
    float* out_loss    = (out_size > centers_elems) ? out : nullptr;

    ema_lastidx_kernel<<<(NSAMP + 511) / 512, 512>>>(labels);
    ema_fused_kernel<<<NUM_CLASS + NLOSS_BLOCKS, 256>>>(x, labels, centers,
                                                        out_loss, out_centers);
}

// round 6
// speedup vs baseline: 1.1711x; 1.0656x over previous
#include <cuda_runtime.h>
#include <cuda_bf16.h>
#include <cstddef>

#define NUM_CLASS 1000
#define DIMS      2048
#define HEADSZ    256
#define NSAMP     16384
#define ALPHA_F   0.999f

#define SAMPLES_PER_BLOCK 8
#define NPAIRS (SAMPLES_PER_BLOCK / 2)             // 4
#define NLOSS_BLOCKS (NSAMP / SAMPLES_PER_BLOCK)   // 2048

// Scratch (__device__ globals; zero-init is the valid empty state, and the
// kernels self-reset everything for the next graph replay).
__device__ int    g_last_idx[NUM_CLASS];   // stores sample_index+1; 0 = empty
__device__ double g_loss_accum;
__device__ int    g_ticket;

// ---------------------------------------------------------------------------
// Kernel A: last-write-wins index per class, from labels only (64 KB read).
// ---------------------------------------------------------------------------
__global__ __launch_bounds__(512) void ema_lastidx_kernel(
    const int* __restrict__ labels)
{
    const int n = blockIdx.x * 512 + threadIdx.x;
    if (n < NSAMP) {
        atomicMax(&g_last_idx[labels[n]], n + 1);
    }
}

// ---------------------------------------------------------------------------
// Kernel B (fused):
//   blocks [0, NUM_CLASS)            : EMA scatter update (one class each)
//   blocks [NUM_CLASS, +NLOSS_BLOCKS): SSE for 8 samples
// Loss path pipelines ONLY the x stream (DRAM latency); center rows are
// L2-resident and loaded just-in-time. x uses __ldcs (evict-first) so the
// 128 MB x stream doesn't evict the 8 MB centers hot set from L2.
// ---------------------------------------------------------------------------
__global__ __launch_bounds__(256, 4) void ema_fused_kernel(
    const float* __restrict__ x,
    const int*   __restrict__ labels,
    const float* __restrict__ centers,
    float*       __restrict__ out_loss,      // may be null
    float*       __restrict__ out_centers)
{
    const int b = blockIdx.x;
    const int t = threadIdx.x;

    if (b < NUM_CLASS) {
        // ---------------- update path: one class per block ----------------
        const int c       = b;
        const int last_p1 = g_last_idx[c];   // final: kernel A completed

        const float4* __restrict__ cr = reinterpret_cast<const float4*>(centers + (size_t)c * DIMS);
        float* __restrict__ oc = out_centers + (size_t)c * DIMS;

        if (last_p1 > 0) {
            const float4* __restrict__ xr =
                reinterpret_cast<const float4*>(x + (size_t)(last_p1 - 1) * DIMS);
            const float beta = 1.0f - ALPHA_F;
            const float4 cv0 = cr[t];
            const float4 cv1 = cr[t + 256];
            const float4 xv0 = __ldcs(&xr[t]);
            const float4 xv1 = __ldcs(&xr[t + 256]);
            const int base = t * 4;
            __stcs(&oc[base + 0], ALPHA_F * cv0.x + beta * xv0.x);
            __stcs(&oc[base + 1], ALPHA_F * cv0.y + beta * xv0.y);
            __stcs(&oc[base + 2], ALPHA_F * cv0.z + beta * xv0.z);
            __stcs(&oc[base + 3], ALPHA_F * cv0.w + beta * xv0.w);
            __stcs(&oc[base + 1024], ALPHA_F * cv1.x + beta * xv1.x);
            __stcs(&oc[base + 1025], ALPHA_F * cv1.y + beta * xv1.y);
            __stcs(&oc[base + 1026], ALPHA_F * cv1.z + beta * xv1.z);
            __stcs(&oc[base + 1027], ALPHA_F * cv1.w + beta * xv1.w);
        } else {
            const float4 cv0 = cr[t];
            const float4 cv1 = cr[t + 256];
            const int base = t * 4;
            __stcs(&oc[base + 0], cv0.x);
            __stcs(&oc[base + 1], cv0.y);
            __stcs(&oc[base + 2], cv0.z);
            __stcs(&oc[base + 3], cv0.w);
            __stcs(&oc[base + 1024], cv1.x);
            __stcs(&oc[base + 1025], cv1.y);
            __stcs(&oc[base + 1026], cv1.z);
            __stcs(&oc[base + 1027], cv1.w);
        }

        __syncthreads();
        if (t == 0) g_last_idx[c] = 0;   // self-reset for next replay
        return;
    }

    // ------- loss path: 8 samples, 4 pairs, x-only double buffer -------
    const int bi   = b - NUM_CLASS;
    const int base = bi * SAMPLES_PER_BLOCK;
    const int2* __restrict__ lp = reinterpret_cast<const int2*>(labels + base);

    float4 xbuf[2][4];   // [buf][ sample0{lo,hi}, sample1{lo,hi} ]

#define LOADX(p, buf)                                                            \
    do {                                                                         \
        const float4* __restrict__ xr0 =                                         \
            reinterpret_cast<const float4*>(x + (size_t)(base + 2 * (p)) * DIMS);\
        const float4* __restrict__ xr1 =                                         \
            reinterpret_cast<const float4*>(x + (size_t)(base + 2 * (p) + 1) * DIMS);\
        xbuf[buf][0] = __ldcs(&xr0[t]);                                          \
        xbuf[buf][1] = __ldcs(&xr0[t + 256]);                                    \
        xbuf[buf][2] = __ldcs(&xr1[t]);                                          \
        xbuf[buf][3] = __ldcs(&xr1[t + 256]);                                    \
    } while (0)

#define SQD(a, b)                                                                \
    ((a.x - b.x) * (a.x - b.x) + (a.y - b.y) * (a.y - b.y) +                     \
     (a.z - b.z) * (a.z - b.z) + (a.w - b.w) * (a.w - b.w))

    float s = 0.0f;
    LOADX(0, 0);
#pragma unroll
    for (int p = 0; p < NPAIRS; ++p) {
        const int cur = p & 1;
        if (p + 1 < NPAIRS) {
            LOADX(p + 1, (p + 1) & 1);   // x loads for next pair issue first
        }
        // Center rows: L2-resident, loaded just-in-time (short-lived regs).
        const int2 L = lp[p];
        const float4* __restrict__ cr0 =
            reinterpret_cast<const float4*>(centers + (size_t)L.x * DIMS);
        const float4* __restrict__ cr1 =
            reinterpret_cast<const float4*>(centers + (size_t)L.y * DIMS);
        const float4 c0 = cr0[t];
        const float4 c1 = cr0[t + 256];
        const float4 c2 = cr1[t];
        const float4 c3 = cr1[t + 256];
        s += SQD(xbuf[cur][0], c0);
        s += SQD(xbuf[cur][1], c1);
        s += SQD(xbuf[cur][2], c2);
        s += SQD(xbuf[cur][3], c3);
    }
#undef LOADX
#undef SQD

    // warp reduce
#pragma unroll
    for (int o = 16; o > 0; o >>= 1) s += __shfl_xor_sync(0xFFFFFFFFu, s, o);

    __shared__ float warp_s[8];
    if ((t & 31) == 0) warp_s[t >> 5] = s;
    __syncthreads();

    if (t == 0) {
        float v = warp_s[0] + warp_s[1] + warp_s[2] + warp_s[3]
                + warp_s[4] + warp_s[5] + warp_s[6] + warp_s[7];
        atomicAdd(&g_loss_accum, (double)v);
        __threadfence();
        const int old = atomicAdd(&g_ticket, 1);
        if (old == NLOSS_BLOCKS - 1) {
            if (out_loss != nullptr) {
                *out_loss = (float)(g_loss_accum / ((double)NSAMP * (double)HEADSZ));
            }
            g_loss_accum = 0.0;
            g_ticket     = 0;
        }
    }
}

// ---------------------------------------------------------------------------
extern "C" void kernel_launch(void* const* d_in, const int* in_sizes, int n_in,
                              void* d_out, int out_size) {
    const float* x       = (const float*)d_in[0];
    const int*   labels  = (const int*)  d_in[1];
    const float* centers = (const float*)d_in[2];

    float* out = (float*)d_out;
    const int centers_elems = NUM_CLASS * DIMS;          // 2,048,000
    float* out_centers = out + (out_size - centers_elems);
    float* out_loss    = (out_size > centers_elems) ? out : nullptr;

    ema_lastidx_kernel<<<(NSAMP + 511) / 512, 512>>>(labels);
    ema_fused_kernel<<<NUM_CLASS + NLOSS_BLOCKS, 256>>>(x, labels, centers,
                                                        out_loss, out_centers);
}